// round 7
// baseline (speedup 1.0000x reference)
#include <cuda_runtime.h>
#include <cuda_bf16.h>
#include <cstdint>
#include <cstddef>

// BiLSTM: V=50000 E=100 H=128 B=128 T=1024 C=2, fp32 throughout.
#define Bn 128
#define Tn 1024

typedef unsigned long long ull;

// Scratch (device globals per the no-allocation rule)
__device__ float g_xp[(size_t)2 * Tn * Bn * 512];   // [dir][t][b][512row] (reused both layers)
__device__ float g_h0[(size_t)Bn * Tn * 256];       // [b][t][dir*128+u]   (layer-0 output)
__device__ float g_hfin[2 * Bn * 128];              // [dir][b][u]         (layer-1 final h)

__device__ __forceinline__ void fma2(ull& d, ull a, ull b) {
    asm("fma.rn.f32x2 %0,%1,%2,%0;" : "+l"(d) : "l"(a), "l"(b));
}
__device__ __forceinline__ float hsum2(ull v) {
    float a, b;
    asm("mov.b64 {%0,%1},%2;" : "=f"(a), "=f"(b) : "l"(v));
    return a + b;
}
__device__ __forceinline__ float sigf(float x) {
    return __fdividef(1.f, 1.f + __expf(-x));
}
__device__ __forceinline__ float tanhfast(float x) {
    return __fdividef(2.f, 1.f + __expf(-2.f * x)) - 1.f;
}
__device__ __forceinline__ unsigned s2u(const void* p) {
    unsigned a;
    asm("{.reg .u64 t; cvta.to.shared.u64 t, %1; cvt.u32.u64 %0, t;}" : "=r"(a) : "l"(p));
    return a;
}

// ---------------------------------------------------------------------------
// Input projection GEMM: g_xp[dir][t][b][row] = A[tok]·W[dir][row] + b_ih + b_hh
// LAYER0: A = emb[x[tok]] (K=100, CH=20). LAYER1: A = g_h0[tok] (K=256, CH=32).
// CTA tile: 64 tokens x 128 rows. Thread tile: 4 tok x 8 rows, f32x2 over K.
// ---------------------------------------------------------------------------
template <int K, int CH, bool GATHER>
__global__ void __launch_bounds__(256) proj_kernel(
    const int* __restrict__ x, const float* __restrict__ src,
    const float* __restrict__ Wf, const float* __restrict__ Wr,
    const float* __restrict__ bif, const float* __restrict__ bhf,
    const float* __restrict__ bir, const float* __restrict__ bhr)
{
    const int dir     = blockIdx.z;
    const int tokBase = blockIdx.x * 64;
    const int rowBase = blockIdx.y * 128;
    const float* __restrict__ W  = dir ? Wr  : Wf;
    const float* __restrict__ bi = dir ? bir : bif;
    const float* __restrict__ bh = dir ? bhr : bhf;

    constexpr int CP = CH + 2;  // even pitch: keeps 8B pair alignment, breaks bank patterns
    __shared__ __align__(16) float As[64 * CP];
    __shared__ __align__(16) float Ws[128 * CP];
    __shared__ int xs[64];

    const int tid = threadIdx.x;
    if (GATHER && tid < 64) xs[tid] = x[tokBase + tid];
    __syncthreads();

    const int tg = tid & 15;   // token group: toks tg*4 .. tg*4+3
    const int rg = tid >> 4;   // row group:   rows rg*8 .. rg*8+7

    ull acc[4][8];
#pragma unroll
    for (int i = 0; i < 4; i++)
#pragma unroll
        for (int j = 0; j < 8; j++) acc[i][j] = 0ull;

    for (int kb = 0; kb < K; kb += CH) {
        __syncthreads();
        for (int i = tid; i < 64 * CH; i += 256) {
            int tok = i / CH, k = i - tok * CH;
            float v;
            if (GATHER) v = src[(size_t)xs[tok] * K + kb + k];
            else        v = g_h0[(size_t)(tokBase + tok) * 256 + kb + k];
            As[tok * CP + k] = v;
        }
        for (int i = tid; i < 128 * CH; i += 256) {
            int r = i / CH, k = i - r * CH;
            Ws[r * CP + k] = W[(size_t)(rowBase + r) * K + kb + k];
        }
        __syncthreads();
#pragma unroll
        for (int kp = 0; kp < CH / 2; kp++) {
            ull a[4], w[8];
#pragma unroll
            for (int i = 0; i < 4; i++)
                a[i] = *(const ull*)&As[(tg * 4 + i) * CP + 2 * kp];
#pragma unroll
            for (int j = 0; j < 8; j++)
                w[j] = *(const ull*)&Ws[(rg * 8 + j) * CP + 2 * kp];
#pragma unroll
            for (int i = 0; i < 4; i++)
#pragma unroll
                for (int j = 0; j < 8; j++) fma2(acc[i][j], a[i], w[j]);
        }
    }

    float bias[8];
#pragma unroll
    for (int j = 0; j < 8; j++) {
        int r = rowBase + rg * 8 + j;
        bias[j] = bi[r] + bh[r];
    }
#pragma unroll
    for (int i = 0; i < 4; i++) {
        int tok = tokBase + tg * 4 + i;
        int b = tok >> 10, t = tok & 1023;
        float* o = &g_xp[((size_t)(dir * Tn + t) * Bn + b) * 512 + rowBase + rg * 8];
#pragma unroll
        for (int j = 0; j < 8; j++) o[j] = hsum2(acc[i][j]) + bias[j];
    }
}

// ---------------------------------------------------------------------------
// Recurrence: 2-CTA cluster per (dir, 4-batch group). Each CTA owns 64 hidden
// units (256 gate rows). w_hh rows live in registers (64 f32x2 per thread).
// Per step: matvec (f32x2 over K, h broadcast from smem) -> gates via smem ->
// elementwise -> h written locally + to peer via DSMEM -> barrier.cluster.
// Grid: 128 CTAs (2 dirs x 32 bgroups x 2 ranks), one wave.
// ---------------------------------------------------------------------------
template <int LAYER>
__global__ void __launch_bounds__(256, 1) __cluster_dims__(2, 1, 1)
rec_kernel(const float* __restrict__ Whf, const float* __restrict__ Whr)
{
    const int rank = (int)(blockIdx.x & 1);
    const int cid  = (int)(blockIdx.x >> 1);
    const int dir  = cid >> 5;
    const int b0   = (cid & 31) * 4;
    const int u0   = rank * 64;
    const int tid  = threadIdx.x;
    const int unit = tid & 63;
    const int gate = tid >> 6;
    const int row  = u0 + unit + (gate << 7);  // gate order i,f,g,o
    const float* __restrict__ Wh = dir ? Whr : Whf;

    __shared__ __align__(16) float hsm[2][4][128];  // double-buffered h: [buf][b][k]
    __shared__ __align__(16) float gsm[4][64][4];   // gates: [gate][unit][b]

    // Load this thread's w_hh row into registers as 64 packed pairs.
    ull wp[64];
    {
        const ull* wrow = (const ull*)(Wh + (size_t)row * 128);
#pragma unroll
        for (int kp = 0; kp < 64; kp++) wp[kp] = wrow[kp];
    }

    // h(0) = 0 (own full buffer; peer zeroes its own copy too)
    for (int i = tid; i < 512; i += 256) ((float*)hsm[0])[i] = 0.f;
    __syncthreads();

    // Peer SMEM base for DSMEM h exchange
    unsigned hsm_local = s2u(&hsm[0][0][0]);
    unsigned hsm_peer;
    {
        unsigned prk = (unsigned)(rank ^ 1);
        asm("mapa.shared::cluster.u32 %0, %1, %2;"
            : "=r"(hsm_peer) : "r"(hsm_local), "r"(prk));
    }

    const int  tstep = dir ? -1 : 1;
    int        tcur  = dir ? (Tn - 1) : 0;
    const long dstr  = (long)tstep * Bn * 512;

    const float* xpb = g_xp + ((size_t)(dir * Tn + tcur) * Bn + b0) * 512 + row;
    float xpf[4];
#pragma unroll
    for (int b = 0; b < 4; b++) xpf[b] = xpb[b * 512];

    const int eb = tid >> 6;   // elementwise: batch
    const int eu = tid & 63;   // elementwise: unit (local)
    float creg = 0.f, hreg = 0.f;
    int buf = 0;

    for (int s = 0; s < Tn; s++) {
        // Matvec: gates[row][b] = sum_k w[row][k] * h[b][k], packed over k.
        ull acc0 = 0, acc1 = 0, acc2 = 0, acc3 = 0;
        const float* hb = &hsm[buf][0][0];
#pragma unroll
        for (int kp = 0; kp < 64; kp++) {
            ull h0 = *(const ull*)&hb[0 * 128 + 2 * kp];
            ull h1 = *(const ull*)&hb[1 * 128 + 2 * kp];
            ull h2 = *(const ull*)&hb[2 * 128 + 2 * kp];
            ull h3 = *(const ull*)&hb[3 * 128 + 2 * kp];
            fma2(acc0, wp[kp], h0);
            fma2(acc1, wp[kp], h1);
            fma2(acc2, wp[kp], h2);
            fma2(acc3, wp[kp], h3);
        }
        float g0 = hsum2(acc0) + xpf[0];
        float g1 = hsum2(acc1) + xpf[1];
        float g2 = hsum2(acc2) + xpf[2];
        float g3 = hsum2(acc3) + xpf[3];

        // Prefetch next step's xp (latency hidden by the rest of this step)
        if (s + 1 < Tn) {
            xpb += dstr;
#pragma unroll
            for (int b = 0; b < 4; b++) xpf[b] = xpb[b * 512];
        }

        *(float4*)&gsm[gate][unit][0] = make_float4(g0, g1, g2, g3);
        __syncthreads();

        // Elementwise LSTM cell: thread owns (batch eb, unit eu); c stays in reg.
        float gi = gsm[0][eu][eb];
        float gf = gsm[1][eu][eb];
        float gG = gsm[2][eu][eb];
        float go = gsm[3][eu][eb];
        creg = sigf(gf) * creg + sigf(gi) * tanhfast(gG);
        hreg = sigf(go) * tanhfast(creg);

        const int nb   = buf ^ 1;
        const int hoff = (nb * 4 + eb) * 128 + (u0 + eu);
        ((float*)hsm)[hoff] = hreg;  // own copy
        asm volatile("st.shared::cluster.f32 [%0], %1;"
                     :: "r"(hsm_peer + (unsigned)hoff * 4), "f"(hreg) : "memory");

        if (LAYER == 0) {
            g_h0[((size_t)(b0 + eb) * Tn + tcur) * 256 + dir * 128 + u0 + eu] = hreg;
        }

        // One barrier per step: releases our DSMEM/local h writes, acquires peer's.
        asm volatile("barrier.cluster.arrive.aligned;" ::: "memory");
        asm volatile("barrier.cluster.wait.aligned;"   ::: "memory");

        buf = nb;
        tcur += tstep;
    }

    if (LAYER == 1) {
        g_hfin[(dir * Bn + b0 + eb) * 128 + u0 + eu] = hreg;  // final carry
    }
}

// ---------------------------------------------------------------------------
// FC head: out[b][c] = [hf(b), hb(b)] . fc_w[c] + fc_b[c]
// ---------------------------------------------------------------------------
__global__ void fc_kernel(const float* __restrict__ fcw,
                          const float* __restrict__ fcb,
                          float* __restrict__ out)
{
    int tid = threadIdx.x;            // 256 threads
    int b = tid >> 1, c = tid & 1;
    const float* hf = &g_hfin[b * 128];
    const float* hr = &g_hfin[(Bn + b) * 128];
    const float* w  = &fcw[c * 256];
    float s = fcb[c];
#pragma unroll 8
    for (int j = 0; j < 128; j++) s += hf[j] * w[j];
#pragma unroll 8
    for (int j = 0; j < 128; j++) s += hr[j] * w[128 + j];
    out[b * 2 + c] = s;
}

// ---------------------------------------------------------------------------
extern "C" void kernel_launch(void* const* d_in, const int* in_sizes, int n_in,
                              void* d_out, int out_size)
{
    (void)in_sizes; (void)n_in; (void)out_size;
    const int*   x     = (const int*)  d_in[0];
    const float* emb   = (const float*)d_in[1];
    const float* wih0  = (const float*)d_in[2];
    const float* whh0  = (const float*)d_in[3];
    const float* bih0  = (const float*)d_in[4];
    const float* bhh0  = (const float*)d_in[5];
    const float* wih0r = (const float*)d_in[6];
    const float* whh0r = (const float*)d_in[7];
    const float* bih0r = (const float*)d_in[8];
    const float* bhh0r = (const float*)d_in[9];
    const float* wih1  = (const float*)d_in[10];
    const float* whh1  = (const float*)d_in[11];
    const float* bih1  = (const float*)d_in[12];
    const float* bhh1  = (const float*)d_in[13];
    const float* wih1r = (const float*)d_in[14];
    const float* whh1r = (const float*)d_in[15];
    const float* bih1r = (const float*)d_in[16];
    const float* bhh1r = (const float*)d_in[17];
    const float* fcw   = (const float*)d_in[18];
    const float* fcb   = (const float*)d_in[19];
    float* out = (float*)d_out;

    dim3 blk(256);
    dim3 gp(Bn * Tn / 64, 4, 2);  // (2048 token tiles, 4 row tiles, 2 dirs)

    // layer 0: projection (emb gather, K=100) then recurrence
    proj_kernel<100, 20, true><<<gp, blk>>>(x, emb, wih0, wih0r,
                                            bih0, bhh0, bih0r, bhh0r);
    rec_kernel<0><<<128, blk>>>(whh0, whh0r);

    // layer 1: projection (reads g_h0, K=256) then recurrence (final h only)
    proj_kernel<256, 32, false><<<gp, blk>>>(x, emb, wih1, wih1r,
                                             bih1, bhh1, bih1r, bhh1r);
    rec_kernel<1><<<128, blk>>>(whh1, whh1r);

    // classifier head
    fc_kernel<<<1, 256>>>(fcw, fcb, out);
}

// round 8
// speedup vs baseline: 1.0009x; 1.0009x over previous
#include <cuda_runtime.h>
#include <cuda_bf16.h>
#include <cstdint>
#include <cstddef>

// BiLSTM: V=50000 E=100 H=128 B=128 T=1024 C=2, fp32 throughout.
#define Bn 128
#define Tn 1024

typedef unsigned long long ull;

// Scratch (device globals per the no-allocation rule)
__device__ float g_xp[(size_t)2 * Tn * Bn * 512];   // [dir][t][b][512row] (reused both layers)
__device__ float g_h0[(size_t)Bn * Tn * 256];       // [b][t][dir*128+u]   (layer-0 output)
__device__ float g_hfin[2 * Bn * 128];              // [dir][b][u]         (layer-1 final h)

__device__ __forceinline__ void fma2(ull& d, ull a, ull b) {
    asm("fma.rn.f32x2 %0,%1,%2,%0;" : "+l"(d) : "l"(a), "l"(b));
}
__device__ __forceinline__ float hsum2(ull v) {
    float a, b;
    asm("mov.b64 {%0,%1},%2;" : "=f"(a), "=f"(b) : "l"(v));
    return a + b;
}
__device__ __forceinline__ float sigf(float x) {
    return __fdividef(1.f, 1.f + __expf(-x));
}
__device__ __forceinline__ float tanhfast(float x) {
    return __fdividef(2.f, 1.f + __expf(-2.f * x)) - 1.f;
}
__device__ __forceinline__ unsigned s2u(const void* p) {
    unsigned a;
    asm("{.reg .u64 t; cvta.to.shared.u64 t, %1; cvt.u32.u64 %0, t;}" : "=r"(a) : "l"(p));
    return a;
}

// ---------------------------------------------------------------------------
// Input projection GEMM: g_xp[dir][t][b][row] = A[tok]·W[dir][row] + b_ih + b_hh
// LAYER0: A = emb[x[tok]] (K=100, CH=20). LAYER1: A = g_h0[tok] (K=256, CH=32).
// CTA tile: 64 tokens x 128 rows. Thread tile: 4 tok x 8 rows, f32x2 over K.
// ---------------------------------------------------------------------------
template <int K, int CH, bool GATHER>
__global__ void __launch_bounds__(256) proj_kernel(
    const int* __restrict__ x, const float* __restrict__ src,
    const float* __restrict__ Wf, const float* __restrict__ Wr,
    const float* __restrict__ bif, const float* __restrict__ bhf,
    const float* __restrict__ bir, const float* __restrict__ bhr)
{
    const int dir     = blockIdx.z;
    const int tokBase = blockIdx.x * 64;
    const int rowBase = blockIdx.y * 128;
    const float* __restrict__ W  = dir ? Wr  : Wf;
    const float* __restrict__ bi = dir ? bir : bif;
    const float* __restrict__ bh = dir ? bhr : bhf;

    constexpr int CP = CH + 2;  // even pitch: keeps 8B pair alignment, breaks bank patterns
    __shared__ __align__(16) float As[64 * CP];
    __shared__ __align__(16) float Ws[128 * CP];
    __shared__ int xs[64];

    const int tid = threadIdx.x;
    if (GATHER && tid < 64) xs[tid] = x[tokBase + tid];
    __syncthreads();

    const int tg = tid & 15;   // token group: toks tg*4 .. tg*4+3
    const int rg = tid >> 4;   // row group:   rows rg*8 .. rg*8+7

    ull acc[4][8];
#pragma unroll
    for (int i = 0; i < 4; i++)
#pragma unroll
        for (int j = 0; j < 8; j++) acc[i][j] = 0ull;

    for (int kb = 0; kb < K; kb += CH) {
        __syncthreads();
        for (int i = tid; i < 64 * CH; i += 256) {
            int tok = i / CH, k = i - tok * CH;
            float v;
            if (GATHER) v = src[(size_t)xs[tok] * K + kb + k];
            else        v = g_h0[(size_t)(tokBase + tok) * 256 + kb + k];
            As[tok * CP + k] = v;
        }
        for (int i = tid; i < 128 * CH; i += 256) {
            int r = i / CH, k = i - r * CH;
            Ws[r * CP + k] = W[(size_t)(rowBase + r) * K + kb + k];
        }
        __syncthreads();
#pragma unroll
        for (int kp = 0; kp < CH / 2; kp++) {
            ull a[4], w[8];
#pragma unroll
            for (int i = 0; i < 4; i++)
                a[i] = *(const ull*)&As[(tg * 4 + i) * CP + 2 * kp];
#pragma unroll
            for (int j = 0; j < 8; j++)
                w[j] = *(const ull*)&Ws[(rg * 8 + j) * CP + 2 * kp];
#pragma unroll
            for (int i = 0; i < 4; i++)
#pragma unroll
                for (int j = 0; j < 8; j++) fma2(acc[i][j], a[i], w[j]);
        }
    }

    float bias[8];
#pragma unroll
    for (int j = 0; j < 8; j++) {
        int r = rowBase + rg * 8 + j;
        bias[j] = bi[r] + bh[r];
    }
#pragma unroll
    for (int i = 0; i < 4; i++) {
        int tok = tokBase + tg * 4 + i;
        int b = tok >> 10, t = tok & 1023;
        float* o = &g_xp[((size_t)(dir * Tn + t) * Bn + b) * 512 + rowBase + rg * 8];
#pragma unroll
        for (int j = 0; j < 8; j++) o[j] = hsum2(acc[i][j]) + bias[j];
    }
}

// ---------------------------------------------------------------------------
// Recurrence: 2-CTA cluster per (dir, 4-batch group). Each CTA owns 64 hidden
// units (256 gate rows). w_hh rows live in registers (64 f32x2 per thread).
// Per step: matvec (f32x2 over K, h broadcast from smem) -> gates via smem ->
// elementwise -> h written locally + to peer via DSMEM -> barrier.cluster.
// Grid: 128 CTAs (2 dirs x 32 bgroups x 2 ranks), one wave.
// ---------------------------------------------------------------------------
template <int LAYER>
__global__ void __launch_bounds__(256, 1) __cluster_dims__(2, 1, 1)
rec_kernel(const float* __restrict__ Whf, const float* __restrict__ Whr)
{
    const int rank = (int)(blockIdx.x & 1);
    const int cid  = (int)(blockIdx.x >> 1);
    const int dir  = cid >> 5;
    const int b0   = (cid & 31) * 4;
    const int u0   = rank * 64;
    const int tid  = threadIdx.x;
    const int unit = tid & 63;
    const int gate = tid >> 6;
    const int row  = u0 + unit + (gate << 7);  // gate order i,f,g,o
    const float* __restrict__ Wh = dir ? Whr : Whf;

    __shared__ __align__(16) float hsm[2][4][128];  // double-buffered h: [buf][b][k]
    __shared__ __align__(16) float gsm[4][64][4];   // gates: [gate][unit][b]

    // Load this thread's w_hh row into registers as 64 packed pairs.
    ull wp[64];
    {
        const ull* wrow = (const ull*)(Wh + (size_t)row * 128);
#pragma unroll
        for (int kp = 0; kp < 64; kp++) wp[kp] = wrow[kp];
    }

    // h(0) = 0 (own full buffer; peer zeroes its own copy too)
    for (int i = tid; i < 512; i += 256) ((float*)hsm[0])[i] = 0.f;
    __syncthreads();

    // Peer SMEM base for DSMEM h exchange
    unsigned hsm_local = s2u(&hsm[0][0][0]);
    unsigned hsm_peer;
    {
        unsigned prk = (unsigned)(rank ^ 1);
        asm("mapa.shared::cluster.u32 %0, %1, %2;"
            : "=r"(hsm_peer) : "r"(hsm_local), "r"(prk));
    }

    const int  tstep = dir ? -1 : 1;
    int        tcur  = dir ? (Tn - 1) : 0;
    const long dstr  = (long)tstep * Bn * 512;

    const float* xpb = g_xp + ((size_t)(dir * Tn + tcur) * Bn + b0) * 512 + row;
    float xpf[4];
#pragma unroll
    for (int b = 0; b < 4; b++) xpf[b] = xpb[b * 512];

    const int eb = tid >> 6;   // elementwise: batch
    const int eu = tid & 63;   // elementwise: unit (local)
    float creg = 0.f, hreg = 0.f;
    int buf = 0;

    for (int s = 0; s < Tn; s++) {
        // Matvec: gates[row][b] = sum_k w[row][k] * h[b][k], packed over k.
        ull acc0 = 0, acc1 = 0, acc2 = 0, acc3 = 0;
        const float* hb = &hsm[buf][0][0];
#pragma unroll
        for (int kp = 0; kp < 64; kp++) {
            ull h0 = *(const ull*)&hb[0 * 128 + 2 * kp];
            ull h1 = *(const ull*)&hb[1 * 128 + 2 * kp];
            ull h2 = *(const ull*)&hb[2 * 128 + 2 * kp];
            ull h3 = *(const ull*)&hb[3 * 128 + 2 * kp];
            fma2(acc0, wp[kp], h0);
            fma2(acc1, wp[kp], h1);
            fma2(acc2, wp[kp], h2);
            fma2(acc3, wp[kp], h3);
        }
        float g0 = hsum2(acc0) + xpf[0];
        float g1 = hsum2(acc1) + xpf[1];
        float g2 = hsum2(acc2) + xpf[2];
        float g3 = hsum2(acc3) + xpf[3];

        // Prefetch next step's xp (latency hidden by the rest of this step)
        if (s + 1 < Tn) {
            xpb += dstr;
#pragma unroll
            for (int b = 0; b < 4; b++) xpf[b] = xpb[b * 512];
        }

        *(float4*)&gsm[gate][unit][0] = make_float4(g0, g1, g2, g3);
        __syncthreads();

        // Elementwise LSTM cell: thread owns (batch eb, unit eu); c stays in reg.
        float gi = gsm[0][eu][eb];
        float gf = gsm[1][eu][eb];
        float gG = gsm[2][eu][eb];
        float go = gsm[3][eu][eb];
        creg = sigf(gf) * creg + sigf(gi) * tanhfast(gG);
        hreg = sigf(go) * tanhfast(creg);

        const int nb   = buf ^ 1;
        const int hoff = (nb * 4 + eb) * 128 + (u0 + eu);
        ((float*)hsm)[hoff] = hreg;  // own copy
        asm volatile("st.shared::cluster.f32 [%0], %1;"
                     :: "r"(hsm_peer + (unsigned)hoff * 4), "f"(hreg) : "memory");

        if (LAYER == 0) {
            g_h0[((size_t)(b0 + eb) * Tn + tcur) * 256 + dir * 128 + u0 + eu] = hreg;
        }

        // One barrier per step: releases our DSMEM/local h writes, acquires peer's.
        asm volatile("barrier.cluster.arrive.aligned;" ::: "memory");
        asm volatile("barrier.cluster.wait.aligned;"   ::: "memory");

        buf = nb;
        tcur += tstep;
    }

    if (LAYER == 1) {
        g_hfin[(dir * Bn + b0 + eb) * 128 + u0 + eu] = hreg;  // final carry
    }
}

// ---------------------------------------------------------------------------
// FC head: out[b][c] = [hf(b), hb(b)] . fc_w[c] + fc_b[c]
// ---------------------------------------------------------------------------
__global__ void fc_kernel(const float* __restrict__ fcw,
                          const float* __restrict__ fcb,
                          float* __restrict__ out)
{
    int tid = threadIdx.x;            // 256 threads
    int b = tid >> 1, c = tid & 1;
    const float* hf = &g_hfin[b * 128];
    const float* hr = &g_hfin[(Bn + b) * 128];
    const float* w  = &fcw[c * 256];
    float s = fcb[c];
#pragma unroll 8
    for (int j = 0; j < 128; j++) s += hf[j] * w[j];
#pragma unroll 8
    for (int j = 0; j < 128; j++) s += hr[j] * w[128 + j];
    out[b * 2 + c] = s;
}

// ---------------------------------------------------------------------------
extern "C" void kernel_launch(void* const* d_in, const int* in_sizes, int n_in,
                              void* d_out, int out_size)
{
    (void)in_sizes; (void)n_in; (void)out_size;
    const int*   x     = (const int*)  d_in[0];
    const float* emb   = (const float*)d_in[1];
    const float* wih0  = (const float*)d_in[2];
    const float* whh0  = (const float*)d_in[3];
    const float* bih0  = (const float*)d_in[4];
    const float* bhh0  = (const float*)d_in[5];
    const float* wih0r = (const float*)d_in[6];
    const float* whh0r = (const float*)d_in[7];
    const float* bih0r = (const float*)d_in[8];
    const float* bhh0r = (const float*)d_in[9];
    const float* wih1  = (const float*)d_in[10];
    const float* whh1  = (const float*)d_in[11];
    const float* bih1  = (const float*)d_in[12];
    const float* bhh1  = (const float*)d_in[13];
    const float* wih1r = (const float*)d_in[14];
    const float* whh1r = (const float*)d_in[15];
    const float* bih1r = (const float*)d_in[16];
    const float* bhh1r = (const float*)d_in[17];
    const float* fcw   = (const float*)d_in[18];
    const float* fcb   = (const float*)d_in[19];
    float* out = (float*)d_out;

    dim3 blk(256);
    dim3 gp(Bn * Tn / 64, 4, 2);  // (2048 token tiles, 4 row tiles, 2 dirs)

    // layer 0: projection (emb gather, K=100) then recurrence
    proj_kernel<100, 20, true><<<gp, blk>>>(x, emb, wih0, wih0r,
                                            bih0, bhh0, bih0r, bhh0r);
    rec_kernel<0><<<128, blk>>>(whh0, whh0r);

    // layer 1: projection (reads g_h0, K=256) then recurrence (final h only)
    proj_kernel<256, 32, false><<<gp, blk>>>(x, emb, wih1, wih1r,
                                             bih1, bhh1, bih1r, bhh1r);
    rec_kernel<1><<<128, blk>>>(whh1, whh1r);

    // classifier head
    fc_kernel<<<1, 256>>>(fcw, fcb, out);
}

// round 9
// speedup vs baseline: 1.2119x; 1.2108x over previous
#include <cuda_runtime.h>
#include <cuda_bf16.h>
#include <cstdint>
#include <cstddef>

#define Bn 128
#define Tn 1024
typedef unsigned long long ull;

__device__ float g_xp[(size_t)2 * Tn * Bn * 512];
__device__ float g_h0[(size_t)Bn * Tn * 256];
__device__ float g_hfin[2 * Bn * 128];

__device__ __forceinline__ void fma2(ull& d, ull a, ull b) {
    asm("fma.rn.f32x2 %0,%1,%2,%0;" : "+l"(d) : "l"(a), "l"(b));
}
__device__ __forceinline__ float hsum2(ull v) {
    float a, b; asm("mov.b64 {%0,%1},%2;" : "=f"(a), "=f"(b) : "l"(v)); return a + b;
}
__device__ __forceinline__ float sigf(float x) { return __fdividef(1.f, 1.f + __expf(-x)); }
__device__ __forceinline__ float tanhfast(float x) {
    return __fdividef(2.f, 1.f + __expf(-2.f * x)) - 1.f;
}
__device__ __forceinline__ unsigned s2u(const void* p) {
    unsigned a;
    asm("{.reg .u64 t; cvta.to.shared.u64 t, %1; cvt.u32.u64 %0, t;}" : "=r"(a) : "l"(p));
    return a;
}
__device__ __forceinline__ void cp8(void* s, const void* g) {
    asm volatile("cp.async.ca.shared.global [%0], [%1], 8;"
                 :: "r"(s2u(s)), "l"(g) : "memory");
}

// ---------------------------------------------------------------------------
// Projection: g_xp[dir][t][b][row] = A[tok]·W[row] + b_ih + b_hh
// Double-buffered cp.async K-chunks. CTA: 64 tok x 128 rows; thread 4x8 f32x2.
// ---------------------------------------------------------------------------
template <int K, int CH, bool GATHER>
__global__ void __launch_bounds__(256) proj_kernel(
    const int* __restrict__ x, const float* __restrict__ src,
    const float* __restrict__ Wf, const float* __restrict__ Wr,
    const float* __restrict__ bif, const float* __restrict__ bhf,
    const float* __restrict__ bir, const float* __restrict__ bhr)
{
    const int dir     = blockIdx.z;
    const int tokBase = blockIdx.x * 64;
    const int rowBase = blockIdx.y * 128;
    const float* __restrict__ W  = dir ? Wr  : Wf;
    const float* __restrict__ bi = dir ? bir : bif;
    const float* __restrict__ bh = dir ? bhr : bhf;

    constexpr int CP  = CH + 2;   // even pitch: 8B-aligned, conflict-free strides
    constexpr int CH2 = CH / 2;
    constexpr int NC  = K / CH;
    __shared__ __align__(16) float As[2][64 * CP];
    __shared__ __align__(16) float Ws[2][128 * CP];
    __shared__ int xs[64];

    const int tid = threadIdx.x;
    if (GATHER && tid < 64) xs[tid] = x[tokBase + tid];
    __syncthreads();

    auto pre = [&](int c, int buf) {
        const int kb = c * CH;
        for (int p = tid; p < 64 * CH2; p += 256) {
            int tok = p / CH2, kp = p - tok * CH2;
            const float* g = GATHER ? src + (size_t)xs[tok] * K + kb + 2 * kp
                                    : g_h0 + (size_t)(tokBase + tok) * 256 + kb + 2 * kp;
            cp8(&As[buf][tok * CP + 2 * kp], g);
        }
        for (int p = tid; p < 128 * CH2; p += 256) {
            int r = p / CH2, kp = p - r * CH2;
            cp8(&Ws[buf][r * CP + 2 * kp], W + (size_t)(rowBase + r) * K + kb + 2 * kp);
        }
        asm volatile("cp.async.commit_group;" ::: "memory");
    };

    const int tg = tid & 15;
    const int rg = tid >> 4;

    ull acc[4][8];
#pragma unroll
    for (int i = 0; i < 4; i++)
#pragma unroll
        for (int j = 0; j < 8; j++) acc[i][j] = 0ull;

    pre(0, 0);
    for (int c = 0; c < NC; c++) {
        asm volatile("cp.async.wait_group 0;" ::: "memory");
        __syncthreads();
        if (c + 1 < NC) pre(c + 1, (c + 1) & 1);
        const float* Ab = &As[c & 1][0];
        const float* Wb = &Ws[c & 1][0];
#pragma unroll
        for (int kp = 0; kp < CH2; kp++) {
            ull a[4], w[8];
#pragma unroll
            for (int i = 0; i < 4; i++)
                a[i] = *(const ull*)&Ab[(tg * 4 + i) * CP + 2 * kp];
#pragma unroll
            for (int j = 0; j < 8; j++)
                w[j] = *(const ull*)&Wb[(rg * 8 + j) * CP + 2 * kp];
#pragma unroll
            for (int i = 0; i < 4; i++)
#pragma unroll
                for (int j = 0; j < 8; j++) fma2(acc[i][j], a[i], w[j]);
        }
        __syncthreads();
    }

    float bias[8];
#pragma unroll
    for (int j = 0; j < 8; j++) {
        int r = rowBase + rg * 8 + j;
        bias[j] = bi[r] + bh[r];
    }
#pragma unroll
    for (int i = 0; i < 4; i++) {
        int tok = tokBase + tg * 4 + i;
        int b = tok >> 10, t = tok & 1023;
        float* o = &g_xp[((size_t)(dir * Tn + t) * Bn + b) * 512 + rowBase + rg * 8];
#pragma unroll
        for (int j = 0; j < 8; j++) o[j] = hsum2(acc[i][j]) + bias[j];
    }
}

// ---------------------------------------------------------------------------
// Recurrence: 2-CTA cluster per (dir, 4-batch group); w_hh rows in registers.
// Per step: f32x2 matvec (LDS.128 h) -> gates via smem -> cell -> DSMEM h to
// peer -> mbarrier handshake (release/acquire, replaces 490cyc cluster bar).
// ---------------------------------------------------------------------------
template <int LAYER>
__global__ void __launch_bounds__(256, 1) __cluster_dims__(2, 1, 1)
rec_kernel(const float* __restrict__ Whf, const float* __restrict__ Whr)
{
    const int rank = (int)(blockIdx.x & 1);
    const int cid  = (int)(blockIdx.x >> 1);
    const int dir  = cid >> 5;
    const int b0   = (cid & 31) * 4;
    const int u0   = rank * 64;
    const int tid  = threadIdx.x;
    const int unit = tid & 63;
    const int gate = tid >> 6;
    const int row  = u0 + unit + (gate << 7);   // gate order i,f,g,o
    const float* __restrict__ Wh = dir ? Whr : Whf;

    __shared__ __align__(16) float hsm[2][4][128];
    __shared__ __align__(16) float gsm[4][64][4];
    __shared__ __align__(8)  ull   mbar[1];

    ull wp[64];
    {
        const ull* wrow = (const ull*)(Wh + (size_t)row * 128);
#pragma unroll
        for (int kp = 0; kp < 64; kp++) wp[kp] = wrow[kp];
    }

    for (int i = tid; i < 512; i += 256) ((float*)hsm[0])[i] = 0.f;
    const unsigned mb_l = s2u(mbar);
    if (tid == 0)
        asm volatile("mbarrier.init.shared.b64 [%0], 2;" :: "r"(mb_l) : "memory");

    unsigned hs_peer, mb_self, mb_peer;
    {
        const unsigned hl = s2u(&hsm[0][0][0]);
        asm("mapa.shared::cluster.u32 %0, %1, %2;" : "=r"(hs_peer) : "r"(hl), "r"((unsigned)(rank ^ 1)));
        asm("mapa.shared::cluster.u32 %0, %1, %2;" : "=r"(mb_self) : "r"(mb_l), "r"((unsigned)rank));
        asm("mapa.shared::cluster.u32 %0, %1, %2;" : "=r"(mb_peer) : "r"(mb_l), "r"((unsigned)(rank ^ 1)));
    }
    asm volatile("barrier.cluster.arrive.aligned;" ::: "memory");
    asm volatile("barrier.cluster.wait.aligned;"   ::: "memory");

    const int  tstep = dir ? -1 : 1;
    int        tcur  = dir ? (Tn - 1) : 0;
    const long dstr  = (long)tstep * (Bn * 512);

    const float* xpb = g_xp + ((size_t)(dir * Tn + tcur) * Bn + b0) * 512 + row;
    float xpf[4];
#pragma unroll
    for (int b = 0; b < 4; b++) xpf[b] = xpb[b * 512];

    const int eb = tid >> 6;
    const int eu = tid & 63;
    float creg = 0.f, hreg = 0.f;
    int buf = 0;

    for (int s = 0; s < Tn; s++) {
        ull acc0 = 0, acc1 = 0, acc2 = 0, acc3 = 0;
        const ulonglong2* h0 = (const ulonglong2*)&hsm[buf][0][0];
        const ulonglong2* h1 = (const ulonglong2*)&hsm[buf][1][0];
        const ulonglong2* h2 = (const ulonglong2*)&hsm[buf][2][0];
        const ulonglong2* h3 = (const ulonglong2*)&hsm[buf][3][0];
#pragma unroll
        for (int kq = 0; kq < 32; kq++) {
            ulonglong2 v0 = h0[kq], v1 = h1[kq], v2 = h2[kq], v3 = h3[kq];
            fma2(acc0, wp[2 * kq], v0.x); fma2(acc0, wp[2 * kq + 1], v0.y);
            fma2(acc1, wp[2 * kq], v1.x); fma2(acc1, wp[2 * kq + 1], v1.y);
            fma2(acc2, wp[2 * kq], v2.x); fma2(acc2, wp[2 * kq + 1], v2.y);
            fma2(acc3, wp[2 * kq], v3.x); fma2(acc3, wp[2 * kq + 1], v3.y);
        }
        float g0 = hsum2(acc0) + xpf[0];
        float g1 = hsum2(acc1) + xpf[1];
        float g2 = hsum2(acc2) + xpf[2];
        float g3 = hsum2(acc3) + xpf[3];

        if (s + 1 < Tn) {
            xpb += dstr;
#pragma unroll
            for (int b = 0; b < 4; b++) xpf[b] = xpb[b * 512];
        }

        *(float4*)&gsm[gate][unit][0] = make_float4(g0, g1, g2, g3);
        __syncthreads();

        float gi = gsm[0][eu][eb], gf = gsm[1][eu][eb],
              gG = gsm[2][eu][eb], go = gsm[3][eu][eb];
        creg = sigf(gf) * creg + sigf(gi) * tanhfast(gG);
        hreg = sigf(go) * tanhfast(creg);

        const int nb   = buf ^ 1;
        const int hoff = (nb * 4 + eb) * 128 + (u0 + eu);
        ((float*)hsm)[hoff] = hreg;                         // local copy
        asm volatile("st.shared::cluster.f32 [%0], %1;"     // peer copy (DSMEM)
                     :: "r"(hs_peer + (unsigned)hoff * 4), "f"(hreg) : "memory");

        if (LAYER == 0)
            g_h0[((size_t)(b0 + eb) * Tn + tcur) * 256 + dir * 128 + u0 + eu] = hreg;

        __syncthreads();  // all h stores issued (cumulativity for the release below)
        if (tid == 0) {
            asm volatile("mbarrier.arrive.release.cluster.shared::cluster.b64 _, [%0];"
                         :: "r"(mb_self) : "memory");
            asm volatile("mbarrier.arrive.release.cluster.shared::cluster.b64 _, [%0];"
                         :: "r"(mb_peer) : "memory");
        }
        {
            unsigned ph = (unsigned)(s & 1);
            asm volatile(
                "{.reg .pred P;\n\tW1%=: mbarrier.try_wait.parity.acquire.cluster.shared::cta.b64 P,[%0],%1;\n\t"
                "@P bra W2%=;\n\tbra W1%=;\n\tW2%=:}"
                :: "r"(mb_l), "r"(ph) : "memory");
        }

        buf = nb;
        tcur += tstep;
    }

    if (LAYER == 1)
        g_hfin[(dir * Bn + b0 + eb) * 128 + u0 + eu] = hreg;
}

// ---------------------------------------------------------------------------
__global__ void fc_kernel(const float* __restrict__ fcw,
                          const float* __restrict__ fcb,
                          float* __restrict__ out)
{
    int tid = threadIdx.x;  // 256 = 128 b x 2 c
    int b = tid >> 1, c = tid & 1;
    const float* hf = &g_hfin[b * 128];
    const float* hr = &g_hfin[(Bn + b) * 128];
    const float* w  = &fcw[c * 256];
    float s = fcb[c];
#pragma unroll 8
    for (int j = 0; j < 128; j++) s += hf[j] * w[j];
#pragma unroll 8
    for (int j = 0; j < 128; j++) s += hr[j] * w[128 + j];
    out[b * 2 + c] = s;
}

// ---------------------------------------------------------------------------
extern "C" void kernel_launch(void* const* d_in, const int* in_sizes, int n_in,
                              void* d_out, int out_size)
{
    (void)in_sizes; (void)n_in; (void)out_size;
    const int*   x     = (const int*)  d_in[0];
    const float* emb   = (const float*)d_in[1];
    const float* wih0  = (const float*)d_in[2];
    const float* whh0  = (const float*)d_in[3];
    const float* bih0  = (const float*)d_in[4];
    const float* bhh0  = (const float*)d_in[5];
    const float* wih0r = (const float*)d_in[6];
    const float* whh0r = (const float*)d_in[7];
    const float* bih0r = (const float*)d_in[8];
    const float* bhh0r = (const float*)d_in[9];
    const float* wih1  = (const float*)d_in[10];
    const float* whh1  = (const float*)d_in[11];
    const float* bih1  = (const float*)d_in[12];
    const float* bhh1  = (const float*)d_in[13];
    const float* wih1r = (const float*)d_in[14];
    const float* whh1r = (const float*)d_in[15];
    const float* bih1r = (const float*)d_in[16];
    const float* bhh1r = (const float*)d_in[17];
    const float* fcw   = (const float*)d_in[18];
    const float* fcb   = (const float*)d_in[19];
    float* out = (float*)d_out;

    dim3 blk(256);
    dim3 gp(Bn * Tn / 64, 4, 2);

    proj_kernel<100, 20, true><<<gp, blk>>>(x, emb, wih0, wih0r,
                                            bih0, bhh0, bih0r, bhh0r);
    rec_kernel<0><<<128, blk>>>(whh0, whh0r);

    proj_kernel<256, 32, false><<<gp, blk>>>(x, emb, wih1, wih1r,
                                             bih1, bhh1, bih1r, bhh1r);
    rec_kernel<1><<<128, blk>>>(whh1, whh1r);

    fc_kernel<<<1, 256>>>(fcw, fcb, out);
}